// round 14
// baseline (speedup 1.0000x reference)
#include <cuda_runtime.h>
#include <cuda_fp16.h>
#include <math.h>

#define MAXN 50000
#define MAXE 800000

// ---------------- scratch (device globals; no allocation allowed) ----------------
__device__ __half g_xl1h[MAXN * 128];
__device__ float g_xr1[MAXN * 128];
__device__ float g_res[MAXN * 32];
__device__ float g_agg1[MAXN * 128];   // normalized conv1 output (pre-bias)
__device__ __half g_xl2h[MAXN * 32];
__device__ float g_xr2[MAXN * 32];
__device__ float g_agg2[MAXN * 32];    // normalized conv2 output (pre-bias)
__device__ double g_sum1[128], g_sq1[128];
__device__ double g_sum2[32], g_sq2[32];
__device__ float g_scale1[128], g_shift1[128];
__device__ float g_scale2[32], g_shift2[32];
// CSR-by-destination (real edges only; self-loops handled inline)
__device__ int g_count[MAXN];
__device__ int g_off[MAXN];
__device__ int g_cursor[MAXN];
__device__ int g_total;
__device__ int g_csr[MAXE];

// ---------------- CSR build ----------------
__global__ void csr_hist(const int* __restrict__ ei, int E) {
    int e = blockIdx.x * blockDim.x + threadIdx.x;
    if (e < E) atomicAdd(&g_count[ei[E + e]], 1);
}

// warp-aggregated offset allocation: contiguous slot range per node, order arbitrary
__global__ void csr_alloc(int N) {
    int i = blockIdx.x * blockDim.x + threadIdx.x;
    int lane = threadIdx.x & 31;
    int c = (i < N) ? g_count[i] : 0;
    int pre = c;
    #pragma unroll
    for (int o = 1; o < 32; o <<= 1) {
        int t = __shfl_up_sync(0xffffffffu, pre, o);
        if (lane >= o) pre += t;
    }
    int wsum = __shfl_sync(0xffffffffu, pre, 31);
    int base = 0;
    if (lane == 31) base = atomicAdd(&g_total, wsum);
    base = __shfl_sync(0xffffffffu, base, 31);
    if (i < N) {
        int off = base + pre - c;
        g_off[i] = off;
        g_cursor[i] = off;
    }
}

__global__ void csr_scatter(const int* __restrict__ ei, int E) {
    int e = blockIdx.x * blockDim.x + threadIdx.x;
    if (e >= E) return;
    int s = ei[e], d = ei[E + e];
    int pos = atomicAdd(&g_cursor[d], 1);
    g_csr[pos] = s;
}

// ---------------- fused dense transform: out = X @ W^T (+bias), K=128 ----------------
// Block tile: 128 rows x 64 feats, 256 threads, 8x4 outputs/thread, K-chunk 32.
// Xs row-major [r][k] (STS.128 + broadcast LDS.128, conflict-free).
// WsT k-major [k][f], 3-bit XOR granule swizzle phys_g = g ^ ((k>>2)&7)
// (stores bank-perfect; compute LDS.128 is a 256B permutation => conflict-free).
// o0 written as HALF (o0h); o1/o2 as float. Optional input transform
// (nscale/nshift): v -> elu(v*scale + shift), used for conv2 reading agg1.
__global__ void __launch_bounds__(256) transform_kernel(
    const float* __restrict__ X, int n,
    const float* __restrict__ W0, const float* __restrict__ W1, const float* __restrict__ W2,
    int F0, int F1, int F2,
    const float* __restrict__ b0, const float* __restrict__ b1, const float* __restrict__ b2,
    __half* __restrict__ o0h, float* __restrict__ o1, float* __restrict__ o2,
    int ld0, int ld1, int ld2,
    const float* __restrict__ nscale,
    const float* __restrict__ nshift)
{
    __shared__ float Xs[128][36];   // [row][k-chunk], 144B row stride (16B aligned)
    __shared__ float WsT[32][68];   // [k][feat], granule-swizzled
    const int rb = blockIdx.x * 128;
    const int fb = blockIdx.y * 64;
    const int tid = threadIdx.x;
    const int Ft = F0 + F1 + F2;

    const int tx = tid & 15, ty = tid >> 4;   // tx: 4 feats, ty: 8 rows
    float acc[8][4];
    #pragma unroll
    for (int i = 0; i < 8; i++)
        #pragma unroll
        for (int j = 0; j < 4; j++) acc[i][j] = 0.f;

    for (int kk = 0; kk < 128; kk += 32) {
        // X tile: 128 rows x 32 k = 1024 float4, 4 per thread (conflict-free STS.128)
        #pragma unroll
        for (int it = 0; it < 4; it++) {
            int idx = it * 256 + tid;
            int r = idx >> 3;            // 0..127
            int kc = (idx & 7) << 2;     // 0..28
            float4 v = make_float4(0.f, 0.f, 0.f, 0.f);
            int row = rb + r;
            if (row < n) {
                int c = kk + kc;
                v = *(const float4*)(X + (size_t)row * 128 + c);
                if (nscale) {
                    float4 sc = *(const float4*)(nscale + c);
                    float4 sh = *(const float4*)(nshift + c);
                    float a0 = v.x * sc.x + sh.x;
                    float a1 = v.y * sc.y + sh.y;
                    float a2 = v.z * sc.z + sh.z;
                    float a3 = v.w * sc.w + sh.w;
                    v.x = a0 > 0.f ? a0 : expm1f(a0);
                    v.y = a1 > 0.f ? a1 : expm1f(a1);
                    v.z = a2 > 0.f ? a2 : expm1f(a2);
                    v.w = a3 > 0.f ? a3 : expm1f(a3);
                }
            }
            *(float4*)&Xs[r][kc] = v;
        }
        // W tile: 64 feats x 32 k = 512 float4, 2 per thread; swizzled k-major stores
        #pragma unroll
        for (int it = 0; it < 2; it++) {
            int idx = it * 256 + tid;
            int f = idx >> 3;            // 0..63
            int kc = (idx & 7) << 2;     // 0..28
            int gf = fb + f;
            float4 v = make_float4(0.f, 0.f, 0.f, 0.f);
            const float* Wp = nullptr;
            int lf = gf;
            if (gf < F0) { Wp = W0; }
            else if (gf < F0 + F1) { Wp = W1; lf = gf - F0; }
            else if (gf < Ft) { Wp = W2; lf = gf - F0 - F1; }
            if (Wp) v = *(const float4*)(Wp + (size_t)lf * 128 + kk + kc);
            int g0 = f >> 2, c0 = f & 3;
            float vv[4] = {v.x, v.y, v.z, v.w};
            #pragma unroll
            for (int j = 0; j < 4; j++) {
                int k = kc + j;
                int pg = g0 ^ ((k >> 2) & 7);
                WsT[k][pg * 4 + c0] = vv[j];
            }
        }
        __syncthreads();

        // compute: 4 k per iteration; 8 a-loads + 4 b-loads feed 128 FMA
        #pragma unroll 2
        for (int k4 = 0; k4 < 32; k4 += 4) {
            float4 a4[8];
            #pragma unroll
            for (int i = 0; i < 8; i++)
                a4[i] = *(const float4*)&Xs[ty * 8 + i][k4];
            #pragma unroll
            for (int q = 0; q < 4; q++) {
                int k = k4 + q;
                int pg = tx ^ ((k >> 2) & 7);
                float4 b4 = *(const float4*)&WsT[k][pg * 4];
                #pragma unroll
                for (int i = 0; i < 8; i++) {
                    float av = (q == 0) ? a4[i].x : (q == 1) ? a4[i].y
                             : (q == 2) ? a4[i].z : a4[i].w;
                    acc[i][0] += av * b4.x;
                    acc[i][1] += av * b4.y;
                    acc[i][2] += av * b4.z;
                    acc[i][3] += av * b4.w;
                }
            }
        }
        __syncthreads();
    }

    const int gfb = fb + tx * 4;   // 4 consecutive features; Ft multiple of 4 => no straddle
    if (gfb < Ft) {
        #pragma unroll
        for (int i = 0; i < 8; i++) {
            int row = rb + ty * 8 + i;
            if (row >= n) break;
            if (gfb < F0) {
                float a0 = acc[i][0] + (b0 ? b0[gfb + 0] : 0.f);
                float a1 = acc[i][1] + (b0 ? b0[gfb + 1] : 0.f);
                float a2 = acc[i][2] + (b0 ? b0[gfb + 2] : 0.f);
                float a3 = acc[i][3] + (b0 ? b0[gfb + 3] : 0.f);
                __half2 p0 = __floats2half2_rn(a0, a1);
                __half2 p1 = __floats2half2_rn(a2, a3);
                uint2 u;
                u.x = *reinterpret_cast<unsigned*>(&p0);
                u.y = *reinterpret_cast<unsigned*>(&p1);
                *(uint2*)(o0h + (size_t)row * ld0 + gfb) = u;
            } else if (gfb < F0 + F1) {
                int lf = gfb - F0;
                #pragma unroll
                for (int j = 0; j < 4; j++)
                    o1[(size_t)row * ld1 + lf + j] = acc[i][j] + (b1 ? b1[lf + j] : 0.f);
            } else {
                int lf = gfb - F0 - F1;
                #pragma unroll
                for (int j = 0; j < 4; j++)
                    o2[(size_t)row * ld2 + lf + j] = acc[i][j] + (b2 ? b2[lf + j] : 0.f);
            }
        }
    }
}

// ---------------- conv1 edge term ----------------
__device__ __forceinline__ void term1(
    uint2 u, const float4& xr, const float4& at, float4& acc, float& den)
{
    float2 f0 = __half22float2(*reinterpret_cast<__half2*>(&u.x));
    float2 f1 = __half22float2(*reinterpret_cast<__half2*>(&u.y));
    float m0 = f0.x + xr.x, m1 = f0.y + xr.y, m2 = f1.x + xr.z, m3 = f1.y + xr.w;
    float l = (m0 > 0.f ? m0 : 0.2f * m0) * at.x
            + (m1 > 0.f ? m1 : 0.2f * m1) * at.y
            + (m2 > 0.f ? m2 : 0.2f * m2) * at.z
            + (m3 > 0.f ? m3 : 0.2f * m3) * at.w;
    l += __shfl_xor_sync(0xffffffffu, l, 1);
    l += __shfl_xor_sync(0xffffffffu, l, 2);
    l += __shfl_xor_sync(0xffffffffu, l, 4);
    float a = __expf(l);
    acc.x += a * f0.x; acc.y += a * f0.y; acc.z += a * f1.x; acc.w += a * f1.y;
    den += a;
}

// ---------------- conv1 aggregation: warp per node, 1-deep software pipeline ----------------
__global__ void agg_conv1(int N, const float* __restrict__ att)
{
    int w = (blockIdx.x * blockDim.x + threadIdx.x) >> 5;
    int lane = threadIdx.x & 31;
    if (w >= N) return;
    int beg = g_off[w], end = beg + g_count[w];

    float4 xr = *(const float4*)(g_xr1 + (size_t)w * 128 + lane * 4);
    float4 at = *(const float4*)(att + lane * 4);
    float4 acc = make_float4(0.f, 0.f, 0.f, 0.f);
    float den = 0.f;

    uint2 u_next = make_uint2(0u, 0u);
    if (beg < end) {
        int s0 = g_csr[beg];
        u_next = *(const uint2*)(g_xl1h + (size_t)s0 * 128 + lane * 4);
    }
    {
        uint2 u = *(const uint2*)(g_xl1h + (size_t)w * 128 + lane * 4);
        term1(u, xr, at, acc, den);   // implicit self-loop
    }
    for (int j = beg; j < end; j++) {
        uint2 u = u_next;
        if (j + 1 < end) {
            int sn = g_csr[j + 1];
            u_next = *(const uint2*)(g_xl1h + (size_t)sn * 128 + lane * 4);
        }
        term1(u, xr, at, acc, den);
    }
    float inv = __fdividef(1.f, den + 1e-16f);
    acc.x *= inv; acc.y *= inv; acc.z *= inv; acc.w *= inv;
    *(float4*)(g_agg1 + (size_t)w * 128 + lane * 4) = acc;
}

// ---------------- conv2 aggregation: warp per node, 4 edges per iteration ----------------
__global__ void agg_conv2(int N, const float* __restrict__ att)
{
    int w = (blockIdx.x * blockDim.x + threadIdx.x) >> 5;
    int lane = threadIdx.x & 31;
    if (w >= N) return;
    int beg = g_off[w];
    int T = g_count[w] + 1;
    int grp = lane >> 3, sl = lane & 7;

    float4 xr = *(const float4*)(g_xr2 + (size_t)w * 32 + sl * 4);
    float4 at = *(const float4*)(att + sl * 4);
    float4 acc = make_float4(0.f, 0.f, 0.f, 0.f);
    float den = 0.f;

    for (int t0 = 0; t0 < T; t0 += 4) {
        int t = t0 + grp;
        bool valid = t < T;
        int s = w;
        if (valid && t > 0) s = g_csr[beg + t - 1];
        uint2 u = *(const uint2*)(g_xl2h + (size_t)s * 32 + sl * 4);
        float2 f0 = __half22float2(*reinterpret_cast<__half2*>(&u.x));
        float2 f1 = __half22float2(*reinterpret_cast<__half2*>(&u.y));
        float m0 = f0.x + xr.x, m1 = f0.y + xr.y, m2 = f1.x + xr.z, m3 = f1.y + xr.w;
        float l = (m0 > 0.f ? m0 : 0.2f * m0) * at.x
                + (m1 > 0.f ? m1 : 0.2f * m1) * at.y
                + (m2 > 0.f ? m2 : 0.2f * m2) * at.z
                + (m3 > 0.f ? m3 : 0.2f * m3) * at.w;
        l += __shfl_xor_sync(0xffffffffu, l, 1);
        l += __shfl_xor_sync(0xffffffffu, l, 2);
        l += __shfl_xor_sync(0xffffffffu, l, 4);
        float a = valid ? __expf(l) : 0.f;
        acc.x += a * f0.x; acc.y += a * f0.y; acc.z += a * f1.x; acc.w += a * f1.y;
        den += a;
    }
    #pragma unroll
    for (int o = 8; o <= 16; o <<= 1) {
        acc.x += __shfl_xor_sync(0xffffffffu, acc.x, o);
        acc.y += __shfl_xor_sync(0xffffffffu, acc.y, o);
        acc.z += __shfl_xor_sync(0xffffffffu, acc.z, o);
        acc.w += __shfl_xor_sync(0xffffffffu, acc.w, o);
        den   += __shfl_xor_sync(0xffffffffu, den, o);
    }
    if (lane < 8) {
        float inv = __fdividef(1.f, den + 1e-16f);
        acc.x *= inv; acc.y *= inv; acc.z *= inv; acc.w *= inv;
        *(float4*)(g_agg2 + (size_t)w * 32 + sl * 4) = acc;
    }
}

// ---------------- batch-norm statistics over raw normalized agg (no bias) ----------------
template <int C>
__global__ void bn_stats(const float* __restrict__ h, int n,
                         double* __restrict__ sum, double* __restrict__ sq)
{
    const int Q = C / 4;
    int tid = threadIdx.x;
    float s0 = 0.f, s1 = 0.f, s2v = 0.f, s3 = 0.f;
    float t0 = 0.f, t1 = 0.f, t2 = 0.f, t3 = 0.f;
    size_t total4 = (size_t)n * Q;
    const float4* h4 = (const float4*)h;
    for (size_t j = (size_t)blockIdx.x * blockDim.x + tid; j < total4;
         j += (size_t)gridDim.x * blockDim.x) {
        float4 v = h4[j];
        s0 += v.x; t0 += v.x * v.x;
        s1 += v.y; t1 += v.y * v.y;
        s2v += v.z; t2 += v.z * v.z;
        s3 += v.w; t3 += v.w * v.w;
    }
    __shared__ float red[8][256];
    red[0][tid] = s0; red[1][tid] = s1; red[2][tid] = s2v; red[3][tid] = s3;
    red[4][tid] = t0; red[5][tid] = t1; red[6][tid] = t2; red[7][tid] = t3;
    __syncthreads();
    int q = tid & (Q - 1);
    if (tid < Q) {
        const int G = 256 / Q;
        #pragma unroll
        for (int k = 0; k < 8; k++) {
            float acc = 0.f;
            for (int r = 0; r < G; r++) acc += red[k][q + r * Q];
            if (k < 4) atomicAdd(&sum[q * 4 + k], (double)acc);
            else       atomicAdd(&sq[q * 4 + (k - 4)], (double)acc);
        }
    }
}

// ---------------- BN prep ----------------
// downstream value = agg*scale + shift; scale = g*rsqrt(var+eps), shift = -mu*scale + b
__global__ void bn_prep(const double* __restrict__ sum, const double* __restrict__ sq,
                        int n, int C,
                        const float* __restrict__ g, const float* __restrict__ b,
                        float* __restrict__ scale, float* __restrict__ shift)
{
    int c = threadIdx.x;
    if (c >= C) return;
    double mu = sum[c] / n;
    double var = sq[c] / n - mu * mu;
    float istd = rsqrtf((float)var + 1e-5f);
    float sc = istd * g[c];
    scale[c] = sc;
    shift[c] = -(float)mu * sc + b[c];
}

// ---------------- final: BN2 + residual + ELU + [N,32]@[32,2] head ----------------
__global__ void finalize_kernel(const float* __restrict__ linW, const float* __restrict__ linb,
                                float* __restrict__ out, int n)
{
    int gw = (blockIdx.x * blockDim.x + threadIdx.x) >> 5;
    int lane = threadIdx.x & 31;
    if (gw >= n) return;
    float v = g_agg2[(size_t)gw * 32 + lane] * g_scale2[lane] + g_shift2[lane]
            + g_res[(size_t)gw * 32 + lane];
    v = v > 0.f ? v : expm1f(v);
    float o0 = v * linW[lane];
    float o1 = v * linW[32 + lane];
    #pragma unroll
    for (int o = 16; o > 0; o >>= 1) {
        o0 += __shfl_xor_sync(0xffffffffu, o0, o);
        o1 += __shfl_xor_sync(0xffffffffu, o1, o);
    }
    if (lane == 0) {
        out[(size_t)gw * 2] = o0 + linb[0];
        out[(size_t)gw * 2 + 1] = o1 + linb[1];
    }
}

// ---------------- host launcher ----------------
extern "C" void kernel_launch(void* const* d_in, const int* in_sizes, int n_in,
                              void* d_out, int out_size)
{
    const float* x      = (const float*)d_in[0];
    const int*   ei     = (const int*)d_in[1];
    const float* Wl1    = (const float*)d_in[2];
    const float* bl1    = (const float*)d_in[3];
    const float* Wr1    = (const float*)d_in[4];
    const float* br1    = (const float*)d_in[5];
    const float* att1   = (const float*)d_in[6];
    const float* Wl2    = (const float*)d_in[8];
    const float* bl2    = (const float*)d_in[9];
    const float* Wr2    = (const float*)d_in[10];
    const float* br2    = (const float*)d_in[11];
    const float* att2   = (const float*)d_in[12];
    const float* bn1_g  = (const float*)d_in[14];
    const float* bn1_b  = (const float*)d_in[15];
    const float* bn2_g  = (const float*)d_in[16];
    const float* bn2_b  = (const float*)d_in[17];
    const float* skipW  = (const float*)d_in[18];
    const float* linW   = (const float*)d_in[19];
    const float* linb   = (const float*)d_in[20];
    float* out = (float*)d_out;
    // bias1/bias2 (d_in[7], d_in[13]) fold out of BN exactly (mean shift)

    const int N = in_sizes[0] / 128;
    const int E = in_sizes[1] / 2;

    void* p;
    cudaGetSymbolAddress(&p, g_count); cudaMemsetAsync(p, 0, (size_t)N * sizeof(int));
    cudaGetSymbolAddress(&p, g_total); cudaMemsetAsync(p, 0, sizeof(int));
    cudaGetSymbolAddress(&p, g_sum1);  cudaMemsetAsync(p, 0, 128 * sizeof(double));
    cudaGetSymbolAddress(&p, g_sq1);   cudaMemsetAsync(p, 0, 128 * sizeof(double));
    cudaGetSymbolAddress(&p, g_sum2);  cudaMemsetAsync(p, 0, 32 * sizeof(double));
    cudaGetSymbolAddress(&p, g_sq2);   cudaMemsetAsync(p, 0, 32 * sizeof(double));

    __half *d_xl1h, *d_xl2h;
    float *d_xr1, *d_res, *d_xr2, *d_agg1, *d_agg2;
    float *d_scale1, *d_shift1, *d_scale2, *d_shift2;
    double *d_sum1, *d_sq1, *d_sum2, *d_sq2;
    cudaGetSymbolAddress((void**)&d_xl1h, g_xl1h);
    cudaGetSymbolAddress((void**)&d_xr1, g_xr1);
    cudaGetSymbolAddress((void**)&d_res, g_res);
    cudaGetSymbolAddress((void**)&d_xl2h, g_xl2h);
    cudaGetSymbolAddress((void**)&d_xr2, g_xr2);
    cudaGetSymbolAddress((void**)&d_agg1, g_agg1);
    cudaGetSymbolAddress((void**)&d_agg2, g_agg2);
    cudaGetSymbolAddress((void**)&d_scale1, g_scale1);
    cudaGetSymbolAddress((void**)&d_shift1, g_shift1);
    cudaGetSymbolAddress((void**)&d_scale2, g_scale2);
    cudaGetSymbolAddress((void**)&d_shift2, g_shift2);
    cudaGetSymbolAddress((void**)&d_sum1, g_sum1);
    cudaGetSymbolAddress((void**)&d_sq1, g_sq1);
    cudaGetSymbolAddress((void**)&d_sum2, g_sum2);
    cudaGetSymbolAddress((void**)&d_sq2, g_sq2);

    const int rowBlocks = (N + 127) / 128;
    const int nodeWarpBlocks = (N * 32 + 255) / 256;

    // ---- CSR build: 3 kernels ----
    csr_hist<<<(E + 255) / 256, 256>>>(ei, E);          // launch 0
    csr_alloc<<<(N + 255) / 256, 256>>>(N);             // launch 1
    csr_scatter<<<(E + 255) / 256, 256>>>(ei, E);       // launch 2

    // conv1 transforms + residual (launch 3 — profiled by ncu)
    transform_kernel<<<dim3(rowBlocks, 5), 256>>>(
        x, N, Wl1, Wr1, skipW, 128, 128, 32,
        bl1, br1, nullptr,
        d_xl1h, d_xr1, d_res, 128, 128, 32,
        nullptr, nullptr);

    agg_conv1<<<nodeWarpBlocks, 256>>>(N, att1);

    bn_stats<128><<<256, 256>>>(d_agg1, N, d_sum1, d_sq1);
    bn_prep<<<1, 128>>>(d_sum1, d_sq1, N, 128, bn1_g, bn1_b, d_scale1, d_shift1);

    // conv2 transforms reading agg1 with on-the-fly BN + ELU
    transform_kernel<<<dim3(rowBlocks, 1), 256>>>(
        d_agg1, N, Wl2, Wr2, nullptr, 32, 32, 0,
        bl2, br2, nullptr,
        d_xl2h, d_xr2, nullptr, 32, 32, 0,
        d_scale1, d_shift1);

    agg_conv2<<<nodeWarpBlocks, 256>>>(N, att2);

    bn_stats<32><<<256, 256>>>(d_agg2, N, d_sum2, d_sq2);
    bn_prep<<<1, 32>>>(d_sum2, d_sq2, N, 32, bn2_g, bn2_b, d_scale2, d_shift2);

    finalize_kernel<<<nodeWarpBlocks, 256>>>(linW, linb, out, N);
}

// round 16
// speedup vs baseline: 1.4235x; 1.4235x over previous
#include <cuda_runtime.h>
#include <cuda_fp16.h>
#include <cstdint>
#include <math.h>

typedef unsigned int u32;

#define MAXN 50000
#define MAXE 800000

// ---------------- scratch (device globals; no allocation allowed) ----------------
__device__ __half g_xl1h[MAXN * 128];
__device__ float g_xr1[MAXN * 128];
__device__ float g_res[MAXN * 32];
__device__ float g_agg1[MAXN * 128];   // normalized conv1 output (pre-bias)
__device__ __half g_xl2h[MAXN * 32];
__device__ float g_xr2[MAXN * 32];
__device__ float g_agg2[MAXN * 32];    // normalized conv2 output (pre-bias)
__device__ double g_sum1[128], g_sq1[128];
__device__ double g_sum2[32], g_sq2[32];
__device__ float g_scale1[128], g_shift1[128];
__device__ float g_scale2[32], g_shift2[32];
// CSR-by-destination (real edges only; self-loops handled inline)
__device__ int g_count[MAXN];
__device__ int g_off[MAXN];
__device__ int g_cursor[MAXN];
__device__ int g_total;
__device__ int g_csr[MAXE];

// ---------------- CSR build ----------------
__global__ void csr_hist(const int* __restrict__ ei, int E) {
    int e = blockIdx.x * blockDim.x + threadIdx.x;
    if (e < E) atomicAdd(&g_count[ei[E + e]], 1);
}

__global__ void csr_alloc(int N) {
    int i = blockIdx.x * blockDim.x + threadIdx.x;
    int lane = threadIdx.x & 31;
    int c = (i < N) ? g_count[i] : 0;
    int pre = c;
    #pragma unroll
    for (int o = 1; o < 32; o <<= 1) {
        int t = __shfl_up_sync(0xffffffffu, pre, o);
        if (lane >= o) pre += t;
    }
    int wsum = __shfl_sync(0xffffffffu, pre, 31);
    int base = 0;
    if (lane == 31) base = atomicAdd(&g_total, wsum);
    base = __shfl_sync(0xffffffffu, base, 31);
    if (i < N) {
        int off = base + pre - c;
        g_off[i] = off;
        g_cursor[i] = off;
    }
}

__global__ void csr_scatter(const int* __restrict__ ei, int E) {
    int e = blockIdx.x * blockDim.x + threadIdx.x;
    if (e >= E) return;
    int s = ei[e], d = ei[E + e];
    int pos = atomicAdd(&g_cursor[d], 1);
    g_csr[pos] = s;
}

// ---------------- tf32 helpers ----------------
__device__ __forceinline__ u32 f2tf32(float f) {
    u32 u;
    asm("cvt.rna.tf32.f32 %0, %1;" : "=r"(u) : "f"(f));
    return u;
}

__device__ __forceinline__ void mma_tf32(float* c, const u32* a, const u32* b) {
    asm volatile(
        "mma.sync.aligned.m16n8k8.row.col.f32.tf32.tf32.f32 "
        "{%0,%1,%2,%3}, {%4,%5,%6,%7}, {%8,%9}, {%0,%1,%2,%3};"
        : "+f"(c[0]), "+f"(c[1]), "+f"(c[2]), "+f"(c[3])
        : "r"(a[0]), "r"(a[1]), "r"(a[2]), "r"(a[3]), "r"(b[0]), "r"(b[1]));
}

// ---------------- fused dense transform via tf32 tensor cores ----------------
// out = X @ W^T (+bias), K=128. Block tile 128 rows x 64 feats, 8 warps (4x2),
// warp tile 32x32 = 2x4 mma.m16n8k8 tiles, K chunked by 32.
// Smem row stride = 36 words for BOTH tiles: fragment scalar loads hit bank
// (lane + const) mod 32 => conflict-free, no swizzle.
// o0 written as HALF (o0h); o1/o2 as float. Optional input transform
// (nscale/nshift): v -> elu(v*scale + shift), used for conv2 reading agg1.
__global__ void __launch_bounds__(256) transform_kernel(
    const float* __restrict__ X, int n,
    const float* __restrict__ W0, const float* __restrict__ W1, const float* __restrict__ W2,
    int F0, int F1, int F2,
    const float* __restrict__ b0, const float* __restrict__ b1, const float* __restrict__ b2,
    __half* __restrict__ o0h, float* __restrict__ o1, float* __restrict__ o2,
    int ld0, int ld1, int ld2,
    const float* __restrict__ nscale,
    const float* __restrict__ nshift)
{
    __shared__ u32 Xs[128][36];   // [row][k], tf32 bits
    __shared__ u32 Wf[64][36];    // [feat][k], tf32 bits (= col-major B)
    const int rb = blockIdx.x * 128;
    const int fb = blockIdx.y * 64;
    const int tid = threadIdx.x;
    const int Ft = F0 + F1 + F2;
    const int wid = tid >> 5, lane = tid & 31;
    const int warp_m = wid & 3, warp_n = wid >> 2;   // 4 x 2 warp grid
    const int gid = lane >> 2, tig = lane & 3;

    float c[2][4][4];
    #pragma unroll
    for (int mt = 0; mt < 2; mt++)
        #pragma unroll
        for (int nt = 0; nt < 4; nt++)
            #pragma unroll
            for (int q = 0; q < 4; q++) c[mt][nt][q] = 0.f;

    for (int kk = 0; kk < 128; kk += 32) {
        // X tile: 128 rows x 32 k = 1024 float4, 4 per thread
        #pragma unroll
        for (int it = 0; it < 4; it++) {
            int idx = it * 256 + tid;
            int r = idx >> 3;            // 0..127
            int kc = (idx & 7) << 2;     // 0..28
            float4 v = make_float4(0.f, 0.f, 0.f, 0.f);
            int row = rb + r;
            if (row < n) {
                int cc = kk + kc;
                v = *(const float4*)(X + (size_t)row * 128 + cc);
                if (nscale) {
                    float4 sc = *(const float4*)(nscale + cc);
                    float4 sh = *(const float4*)(nshift + cc);
                    float a0 = v.x * sc.x + sh.x;
                    float a1 = v.y * sc.y + sh.y;
                    float a2 = v.z * sc.z + sh.z;
                    float a3 = v.w * sc.w + sh.w;
                    v.x = a0 > 0.f ? a0 : expm1f(a0);
                    v.y = a1 > 0.f ? a1 : expm1f(a1);
                    v.z = a2 > 0.f ? a2 : expm1f(a2);
                    v.w = a3 > 0.f ? a3 : expm1f(a3);
                }
            }
            uint4 u;
            u.x = f2tf32(v.x); u.y = f2tf32(v.y);
            u.z = f2tf32(v.z); u.w = f2tf32(v.w);
            *(uint4*)&Xs[r][kc] = u;
        }
        // W tile: 64 feats x 32 k = 512 float4, 2 per thread
        #pragma unroll
        for (int it = 0; it < 2; it++) {
            int idx = it * 256 + tid;
            int f = idx >> 3;            // 0..63
            int kc = (idx & 7) << 2;     // 0..28
            int gf = fb + f;
            float4 v = make_float4(0.f, 0.f, 0.f, 0.f);
            const float* Wp = nullptr;
            int lf = gf;
            if (gf < F0) { Wp = W0; }
            else if (gf < F0 + F1) { Wp = W1; lf = gf - F0; }
            else if (gf < Ft) { Wp = W2; lf = gf - F0 - F1; }
            if (Wp) v = *(const float4*)(Wp + (size_t)lf * 128 + kk + kc);
            uint4 u;
            u.x = f2tf32(v.x); u.y = f2tf32(v.y);
            u.z = f2tf32(v.z); u.w = f2tf32(v.w);
            *(uint4*)&Wf[f][kc] = u;
        }
        __syncthreads();

        #pragma unroll
        for (int k8 = 0; k8 < 32; k8 += 8) {
            int col0 = k8 + tig;
            u32 a[2][4], b[4][2];
            #pragma unroll
            for (int mt = 0; mt < 2; mt++) {
                int r0 = warp_m * 32 + mt * 16 + gid;
                a[mt][0] = Xs[r0][col0];
                a[mt][1] = Xs[r0 + 8][col0];
                a[mt][2] = Xs[r0][col0 + 4];
                a[mt][3] = Xs[r0 + 8][col0 + 4];
            }
            #pragma unroll
            for (int nt = 0; nt < 4; nt++) {
                int f0 = warp_n * 32 + nt * 8 + gid;
                b[nt][0] = Wf[f0][col0];
                b[nt][1] = Wf[f0][col0 + 4];
            }
            #pragma unroll
            for (int mt = 0; mt < 2; mt++)
                #pragma unroll
                for (int nt = 0; nt < 4; nt++)
                    mma_tf32(c[mt][nt], a[mt], b[nt]);
        }
        __syncthreads();
    }

    // epilogue: C tile (mt,nt): rows gid / gid+8, cols 2*tig / 2*tig+1
    #pragma unroll
    for (int nt = 0; nt < 4; nt++) {
        int base = fb + warp_n * 32 + nt * 8;   // 8-col block, never straddles regions
        if (base >= Ft) continue;
        int gfc = base + 2 * tig;
        #pragma unroll
        for (int mt = 0; mt < 2; mt++) {
            int r0 = rb + warp_m * 32 + mt * 16 + gid;
            #pragma unroll
            for (int h = 0; h < 2; h++) {
                int row = r0 + h * 8;
                if (row >= n) continue;
                float v0 = c[mt][nt][h * 2 + 0];
                float v1 = c[mt][nt][h * 2 + 1];
                if (base < F0) {
                    v0 += b0 ? b0[gfc] : 0.f;
                    v1 += b0 ? b0[gfc + 1] : 0.f;
                    __half2 p = __floats2half2_rn(v0, v1);
                    *(__half2*)(o0h + (size_t)row * ld0 + gfc) = p;
                } else if (base < F0 + F1) {
                    int lf = gfc - F0;
                    v0 += b1 ? b1[lf] : 0.f;
                    v1 += b1 ? b1[lf + 1] : 0.f;
                    float2 p = make_float2(v0, v1);
                    *(float2*)(o1 + (size_t)row * ld1 + lf) = p;
                } else {
                    int lf = gfc - F0 - F1;
                    v0 += b2 ? b2[lf] : 0.f;
                    v1 += b2 ? b2[lf + 1] : 0.f;
                    float2 p = make_float2(v0, v1);
                    *(float2*)(o2 + (size_t)row * ld2 + lf) = p;
                }
            }
        }
    }
}

// ---------------- conv1 edge term ----------------
__device__ __forceinline__ void term1(
    uint2 u, const float4& xr, const float4& at, float4& acc, float& den)
{
    float2 f0 = __half22float2(*reinterpret_cast<__half2*>(&u.x));
    float2 f1 = __half22float2(*reinterpret_cast<__half2*>(&u.y));
    float m0 = f0.x + xr.x, m1 = f0.y + xr.y, m2 = f1.x + xr.z, m3 = f1.y + xr.w;
    float l = (m0 > 0.f ? m0 : 0.2f * m0) * at.x
            + (m1 > 0.f ? m1 : 0.2f * m1) * at.y
            + (m2 > 0.f ? m2 : 0.2f * m2) * at.z
            + (m3 > 0.f ? m3 : 0.2f * m3) * at.w;
    l += __shfl_xor_sync(0xffffffffu, l, 1);
    l += __shfl_xor_sync(0xffffffffu, l, 2);
    l += __shfl_xor_sync(0xffffffffu, l, 4);
    float a = __expf(l);
    acc.x += a * f0.x; acc.y += a * f0.y; acc.z += a * f1.x; acc.w += a * f1.y;
    den += a;
}

// ---------------- conv1 aggregation: warp per node, 1-deep software pipeline ----------------
__global__ void agg_conv1(int N, const float* __restrict__ att)
{
    int w = (blockIdx.x * blockDim.x + threadIdx.x) >> 5;
    int lane = threadIdx.x & 31;
    if (w >= N) return;
    int beg = g_off[w], end = beg + g_count[w];

    float4 xr = *(const float4*)(g_xr1 + (size_t)w * 128 + lane * 4);
    float4 at = *(const float4*)(att + lane * 4);
    float4 acc = make_float4(0.f, 0.f, 0.f, 0.f);
    float den = 0.f;

    uint2 u_next = make_uint2(0u, 0u);
    if (beg < end) {
        int s0 = g_csr[beg];
        u_next = *(const uint2*)(g_xl1h + (size_t)s0 * 128 + lane * 4);
    }
    {
        uint2 u = *(const uint2*)(g_xl1h + (size_t)w * 128 + lane * 4);
        term1(u, xr, at, acc, den);   // implicit self-loop
    }
    for (int j = beg; j < end; j++) {
        uint2 u = u_next;
        if (j + 1 < end) {
            int sn = g_csr[j + 1];
            u_next = *(const uint2*)(g_xl1h + (size_t)sn * 128 + lane * 4);
        }
        term1(u, xr, at, acc, den);
    }
    float inv = __fdividef(1.f, den + 1e-16f);
    acc.x *= inv; acc.y *= inv; acc.z *= inv; acc.w *= inv;
    *(float4*)(g_agg1 + (size_t)w * 128 + lane * 4) = acc;
}

// ---------------- conv2 aggregation: warp per node, 4 edges per iteration ----------------
__global__ void agg_conv2(int N, const float* __restrict__ att)
{
    int w = (blockIdx.x * blockDim.x + threadIdx.x) >> 5;
    int lane = threadIdx.x & 31;
    if (w >= N) return;
    int beg = g_off[w];
    int T = g_count[w] + 1;
    int grp = lane >> 3, sl = lane & 7;

    float4 xr = *(const float4*)(g_xr2 + (size_t)w * 32 + sl * 4);
    float4 at = *(const float4*)(att + sl * 4);
    float4 acc = make_float4(0.f, 0.f, 0.f, 0.f);
    float den = 0.f;

    for (int t0 = 0; t0 < T; t0 += 4) {
        int t = t0 + grp;
        bool valid = t < T;
        int s = w;
        if (valid && t > 0) s = g_csr[beg + t - 1];
        uint2 u = *(const uint2*)(g_xl2h + (size_t)s * 32 + sl * 4);
        float2 f0 = __half22float2(*reinterpret_cast<__half2*>(&u.x));
        float2 f1 = __half22float2(*reinterpret_cast<__half2*>(&u.y));
        float m0 = f0.x + xr.x, m1 = f0.y + xr.y, m2 = f1.x + xr.z, m3 = f1.y + xr.w;
        float l = (m0 > 0.f ? m0 : 0.2f * m0) * at.x
                + (m1 > 0.f ? m1 : 0.2f * m1) * at.y
                + (m2 > 0.f ? m2 : 0.2f * m2) * at.z
                + (m3 > 0.f ? m3 : 0.2f * m3) * at.w;
        l += __shfl_xor_sync(0xffffffffu, l, 1);
        l += __shfl_xor_sync(0xffffffffu, l, 2);
        l += __shfl_xor_sync(0xffffffffu, l, 4);
        float a = valid ? __expf(l) : 0.f;
        acc.x += a * f0.x; acc.y += a * f0.y; acc.z += a * f1.x; acc.w += a * f1.y;
        den += a;
    }
    #pragma unroll
    for (int o = 8; o <= 16; o <<= 1) {
        acc.x += __shfl_xor_sync(0xffffffffu, acc.x, o);
        acc.y += __shfl_xor_sync(0xffffffffu, acc.y, o);
        acc.z += __shfl_xor_sync(0xffffffffu, acc.z, o);
        acc.w += __shfl_xor_sync(0xffffffffu, acc.w, o);
        den   += __shfl_xor_sync(0xffffffffu, den, o);
    }
    if (lane < 8) {
        float inv = __fdividef(1.f, den + 1e-16f);
        acc.x *= inv; acc.y *= inv; acc.z *= inv; acc.w *= inv;
        *(float4*)(g_agg2 + (size_t)w * 32 + sl * 4) = acc;
    }
}

// ---------------- batch-norm statistics over raw normalized agg (no bias) ----------------
template <int C>
__global__ void bn_stats(const float* __restrict__ h, int n,
                         double* __restrict__ sum, double* __restrict__ sq)
{
    const int Q = C / 4;
    int tid = threadIdx.x;
    float s0 = 0.f, s1 = 0.f, s2v = 0.f, s3 = 0.f;
    float t0 = 0.f, t1 = 0.f, t2 = 0.f, t3 = 0.f;
    size_t total4 = (size_t)n * Q;
    const float4* h4 = (const float4*)h;
    for (size_t j = (size_t)blockIdx.x * blockDim.x + tid; j < total4;
         j += (size_t)gridDim.x * blockDim.x) {
        float4 v = h4[j];
        s0 += v.x; t0 += v.x * v.x;
        s1 += v.y; t1 += v.y * v.y;
        s2v += v.z; t2 += v.z * v.z;
        s3 += v.w; t3 += v.w * v.w;
    }
    __shared__ float red[8][256];
    red[0][tid] = s0; red[1][tid] = s1; red[2][tid] = s2v; red[3][tid] = s3;
    red[4][tid] = t0; red[5][tid] = t1; red[6][tid] = t2; red[7][tid] = t3;
    __syncthreads();
    int q = tid & (Q - 1);
    if (tid < Q) {
        const int G = 256 / Q;
        #pragma unroll
        for (int k = 0; k < 8; k++) {
            float acc = 0.f;
            for (int r = 0; r < G; r++) acc += red[k][q + r * Q];
            if (k < 4) atomicAdd(&sum[q * 4 + k], (double)acc);
            else       atomicAdd(&sq[q * 4 + (k - 4)], (double)acc);
        }
    }
}

// ---------------- BN prep ----------------
__global__ void bn_prep(const double* __restrict__ sum, const double* __restrict__ sq,
                        int n, int C,
                        const float* __restrict__ g, const float* __restrict__ b,
                        float* __restrict__ scale, float* __restrict__ shift)
{
    int c = threadIdx.x;
    if (c >= C) return;
    double mu = sum[c] / n;
    double var = sq[c] / n - mu * mu;
    float istd = rsqrtf((float)var + 1e-5f);
    float sc = istd * g[c];
    scale[c] = sc;
    shift[c] = -(float)mu * sc + b[c];
}

// ---------------- final: BN2 + residual + ELU + [N,32]@[32,2] head ----------------
__global__ void finalize_kernel(const float* __restrict__ linW, const float* __restrict__ linb,
                                float* __restrict__ out, int n)
{
    int gw = (blockIdx.x * blockDim.x + threadIdx.x) >> 5;
    int lane = threadIdx.x & 31;
    if (gw >= n) return;
    float v = g_agg2[(size_t)gw * 32 + lane] * g_scale2[lane] + g_shift2[lane]
            + g_res[(size_t)gw * 32 + lane];
    v = v > 0.f ? v : expm1f(v);
    float o0 = v * linW[lane];
    float o1 = v * linW[32 + lane];
    #pragma unroll
    for (int o = 16; o > 0; o >>= 1) {
        o0 += __shfl_xor_sync(0xffffffffu, o0, o);
        o1 += __shfl_xor_sync(0xffffffffu, o1, o);
    }
    if (lane == 0) {
        out[(size_t)gw * 2] = o0 + linb[0];
        out[(size_t)gw * 2 + 1] = o1 + linb[1];
    }
}

// ---------------- host launcher ----------------
extern "C" void kernel_launch(void* const* d_in, const int* in_sizes, int n_in,
                              void* d_out, int out_size)
{
    const float* x      = (const float*)d_in[0];
    const int*   ei     = (const int*)d_in[1];
    const float* Wl1    = (const float*)d_in[2];
    const float* bl1    = (const float*)d_in[3];
    const float* Wr1    = (const float*)d_in[4];
    const float* br1    = (const float*)d_in[5];
    const float* att1   = (const float*)d_in[6];
    const float* Wl2    = (const float*)d_in[8];
    const float* bl2    = (const float*)d_in[9];
    const float* Wr2    = (const float*)d_in[10];
    const float* br2    = (const float*)d_in[11];
    const float* att2   = (const float*)d_in[12];
    const float* bn1_g  = (const float*)d_in[14];
    const float* bn1_b  = (const float*)d_in[15];
    const float* bn2_g  = (const float*)d_in[16];
    const float* bn2_b  = (const float*)d_in[17];
    const float* skipW  = (const float*)d_in[18];
    const float* linW   = (const float*)d_in[19];
    const float* linb   = (const float*)d_in[20];
    float* out = (float*)d_out;
    // bias1/bias2 (d_in[7], d_in[13]) fold out of BN exactly (mean shift)

    const int N = in_sizes[0] / 128;
    const int E = in_sizes[1] / 2;

    void* p;
    cudaGetSymbolAddress(&p, g_count); cudaMemsetAsync(p, 0, (size_t)N * sizeof(int));
    cudaGetSymbolAddress(&p, g_total); cudaMemsetAsync(p, 0, sizeof(int));
    cudaGetSymbolAddress(&p, g_sum1);  cudaMemsetAsync(p, 0, 128 * sizeof(double));
    cudaGetSymbolAddress(&p, g_sq1);   cudaMemsetAsync(p, 0, 128 * sizeof(double));
    cudaGetSymbolAddress(&p, g_sum2);  cudaMemsetAsync(p, 0, 32 * sizeof(double));
    cudaGetSymbolAddress(&p, g_sq2);   cudaMemsetAsync(p, 0, 32 * sizeof(double));

    __half *d_xl1h, *d_xl2h;
    float *d_xr1, *d_res, *d_xr2, *d_agg1, *d_agg2;
    float *d_scale1, *d_shift1, *d_scale2, *d_shift2;
    double *d_sum1, *d_sq1, *d_sum2, *d_sq2;
    cudaGetSymbolAddress((void**)&d_xl1h, g_xl1h);
    cudaGetSymbolAddress((void**)&d_xr1, g_xr1);
    cudaGetSymbolAddress((void**)&d_res, g_res);
    cudaGetSymbolAddress((void**)&d_xl2h, g_xl2h);
    cudaGetSymbolAddress((void**)&d_xr2, g_xr2);
    cudaGetSymbolAddress((void**)&d_agg1, g_agg1);
    cudaGetSymbolAddress((void**)&d_agg2, g_agg2);
    cudaGetSymbolAddress((void**)&d_scale1, g_scale1);
    cudaGetSymbolAddress((void**)&d_shift1, g_shift1);
    cudaGetSymbolAddress((void**)&d_scale2, g_scale2);
    cudaGetSymbolAddress((void**)&d_shift2, g_shift2);
    cudaGetSymbolAddress((void**)&d_sum1, g_sum1);
    cudaGetSymbolAddress((void**)&d_sq1, g_sq1);
    cudaGetSymbolAddress((void**)&d_sum2, g_sum2);
    cudaGetSymbolAddress((void**)&d_sq2, g_sq2);

    const int rowBlocks = (N + 127) / 128;
    const int nodeWarpBlocks = (N * 32 + 255) / 256;

    // ---- CSR build: 3 kernels ----
    csr_hist<<<(E + 255) / 256, 256>>>(ei, E);          // launch 0
    csr_alloc<<<(N + 255) / 256, 256>>>(N);             // launch 1
    csr_scatter<<<(E + 255) / 256, 256>>>(ei, E);       // launch 2

    // conv1 transforms + residual (launch 3 — profiled by ncu)
    transform_kernel<<<dim3(rowBlocks, 5), 256>>>(
        x, N, Wl1, Wr1, skipW, 128, 128, 32,
        bl1, br1, nullptr,
        d_xl1h, d_xr1, d_res, 128, 128, 32,
        nullptr, nullptr);

    agg_conv1<<<nodeWarpBlocks, 256>>>(N, att1);

    bn_stats<128><<<256, 256>>>(d_agg1, N, d_sum1, d_sq1);
    bn_prep<<<1, 128>>>(d_sum1, d_sq1, N, 128, bn1_g, bn1_b, d_scale1, d_shift1);

    // conv2 transforms reading agg1 with on-the-fly BN + ELU
    transform_kernel<<<dim3(rowBlocks, 1), 256>>>(
        d_agg1, N, Wl2, Wr2, nullptr, 32, 32, 0,
        bl2, br2, nullptr,
        d_xl2h, d_xr2, nullptr, 32, 32, 0,
        d_scale1, d_shift1);

    agg_conv2<<<nodeWarpBlocks, 256>>>(N, att2);

    bn_stats<32><<<256, 256>>>(d_agg2, N, d_sum2, d_sq2);
    bn_prep<<<1, 32>>>(d_sum2, d_sq2, N, 32, bn2_g, bn2_b, d_scale2, d_shift2);

    finalize_kernel<<<nodeWarpBlocks, 256>>>(linW, linb, out, N);
}

// round 17
// speedup vs baseline: 1.4534x; 1.0210x over previous
#include <cuda_runtime.h>
#include <cuda_fp16.h>
#include <cstdint>
#include <math.h>

typedef unsigned int u32;

#define MAXN 50000
#define MAXE 800000

// ---------------- scratch (device globals; no allocation allowed) ----------------
__device__ __half g_xl1h[MAXN * 128];
__device__ float g_xr1[MAXN * 128];
__device__ float g_res[MAXN * 32];
__device__ float g_agg1[MAXN * 128];   // normalized conv1 output (pre-bias)
__device__ __half g_xl2h[MAXN * 32];
__device__ float g_xr2[MAXN * 32];
__device__ float g_agg2[MAXN * 32];    // normalized conv2 output (pre-bias)
__device__ double g_sum1[128], g_sq1[128];
__device__ double g_sum2[32], g_sq2[32];
__device__ float g_scale1[128], g_shift1[128];
__device__ float g_scale2[32], g_shift2[32];
// CSR-by-destination (real edges only; self-loops handled inline)
__device__ int g_count[MAXN];
__device__ int g_off[MAXN];
__device__ int g_cursor[MAXN];
__device__ int g_total;
__device__ int g_csr[MAXE];

// ---------------- CSR build ----------------
__global__ void csr_hist(const int* __restrict__ ei, int E) {
    int e = blockIdx.x * blockDim.x + threadIdx.x;
    if (e < E) atomicAdd(&g_count[ei[E + e]], 1);
}

__global__ void csr_alloc(int N) {
    int i = blockIdx.x * blockDim.x + threadIdx.x;
    int lane = threadIdx.x & 31;
    int c = (i < N) ? g_count[i] : 0;
    int pre = c;
    #pragma unroll
    for (int o = 1; o < 32; o <<= 1) {
        int t = __shfl_up_sync(0xffffffffu, pre, o);
        if (lane >= o) pre += t;
    }
    int wsum = __shfl_sync(0xffffffffu, pre, 31);
    int base = 0;
    if (lane == 31) base = atomicAdd(&g_total, wsum);
    base = __shfl_sync(0xffffffffu, base, 31);
    if (i < N) {
        int off = base + pre - c;
        g_off[i] = off;
        g_cursor[i] = off;
    }
}

__global__ void csr_scatter(const int* __restrict__ ei, int E) {
    int e = blockIdx.x * blockDim.x + threadIdx.x;
    if (e >= E) return;
    int s = ei[e], d = ei[E + e];
    int pos = atomicAdd(&g_cursor[d], 1);
    g_csr[pos] = s;
}

// ---------------- tf32 helpers ----------------
__device__ __forceinline__ u32 f2tf32(float f) {
    u32 u;
    asm("cvt.rna.tf32.f32 %0, %1;" : "=r"(u) : "f"(f));
    return u;
}

__device__ __forceinline__ void mma_tf32(float* c, const u32* a, const u32* b) {
    asm volatile(
        "mma.sync.aligned.m16n8k8.row.col.f32.tf32.tf32.f32 "
        "{%0,%1,%2,%3}, {%4,%5,%6,%7}, {%8,%9}, {%0,%1,%2,%3};"
        : "+f"(c[0]), "+f"(c[1]), "+f"(c[2]), "+f"(c[3])
        : "r"(a[0]), "r"(a[1]), "r"(a[2]), "r"(a[3]), "r"(b[0]), "r"(b[1]));
}

// ---------------- fused dense transform via tf32 tensor cores ----------------
// out = X @ W^T (+bias), K=128. Block tile 128 rows x 64 feats, 8 warps (4x2),
// warp tile 32x32 = 2x4 mma.m16n8k8 tiles, K chunked by 32.
// Smem row stride = 36 words for BOTH tiles: fragment scalar loads hit bank
// (lane + const) mod 32 => conflict-free, no swizzle.
// o0 written as HALF (o0h); o1/o2 as float. Optional input transform
// (nscale/nshift): v -> elu(v*scale + shift), used for conv2 reading agg1.
__global__ void __launch_bounds__(256) transform_kernel(
    const float* __restrict__ X, int n,
    const float* __restrict__ W0, const float* __restrict__ W1, const float* __restrict__ W2,
    int F0, int F1, int F2,
    const float* __restrict__ b0, const float* __restrict__ b1, const float* __restrict__ b2,
    __half* __restrict__ o0h, float* __restrict__ o1, float* __restrict__ o2,
    int ld0, int ld1, int ld2,
    const float* __restrict__ nscale,
    const float* __restrict__ nshift)
{
    __shared__ u32 Xs[128][36];   // [row][k], tf32 bits
    __shared__ u32 Wf[64][36];    // [feat][k], tf32 bits (= col-major B)
    const int rb = blockIdx.x * 128;
    const int fb = blockIdx.y * 64;
    const int tid = threadIdx.x;
    const int Ft = F0 + F1 + F2;
    const int wid = tid >> 5, lane = tid & 31;
    const int warp_m = wid & 3, warp_n = wid >> 2;   // 4 x 2 warp grid
    const int gid = lane >> 2, tig = lane & 3;

    float c[2][4][4];
    #pragma unroll
    for (int mt = 0; mt < 2; mt++)
        #pragma unroll
        for (int nt = 0; nt < 4; nt++)
            #pragma unroll
            for (int q = 0; q < 4; q++) c[mt][nt][q] = 0.f;

    for (int kk = 0; kk < 128; kk += 32) {
        // X tile: 128 rows x 32 k = 1024 float4, 4 per thread
        #pragma unroll
        for (int it = 0; it < 4; it++) {
            int idx = it * 256 + tid;
            int r = idx >> 3;            // 0..127
            int kc = (idx & 7) << 2;     // 0..28
            float4 v = make_float4(0.f, 0.f, 0.f, 0.f);
            int row = rb + r;
            if (row < n) {
                int cc = kk + kc;
                v = *(const float4*)(X + (size_t)row * 128 + cc);
                if (nscale) {
                    float4 sc = *(const float4*)(nscale + cc);
                    float4 sh = *(const float4*)(nshift + cc);
                    float a0 = v.x * sc.x + sh.x;
                    float a1 = v.y * sc.y + sh.y;
                    float a2 = v.z * sc.z + sh.z;
                    float a3 = v.w * sc.w + sh.w;
                    v.x = a0 > 0.f ? a0 : expm1f(a0);
                    v.y = a1 > 0.f ? a1 : expm1f(a1);
                    v.z = a2 > 0.f ? a2 : expm1f(a2);
                    v.w = a3 > 0.f ? a3 : expm1f(a3);
                }
            }
            uint4 u;
            u.x = f2tf32(v.x); u.y = f2tf32(v.y);
            u.z = f2tf32(v.z); u.w = f2tf32(v.w);
            *(uint4*)&Xs[r][kc] = u;
        }
        // W tile: 64 feats x 32 k = 512 float4, 2 per thread
        #pragma unroll
        for (int it = 0; it < 2; it++) {
            int idx = it * 256 + tid;
            int f = idx >> 3;            // 0..63
            int kc = (idx & 7) << 2;     // 0..28
            int gf = fb + f;
            float4 v = make_float4(0.f, 0.f, 0.f, 0.f);
            const float* Wp = nullptr;
            int lf = gf;
            if (gf < F0) { Wp = W0; }
            else if (gf < F0 + F1) { Wp = W1; lf = gf - F0; }
            else if (gf < Ft) { Wp = W2; lf = gf - F0 - F1; }
            if (Wp) v = *(const float4*)(Wp + (size_t)lf * 128 + kk + kc);
            uint4 u;
            u.x = f2tf32(v.x); u.y = f2tf32(v.y);
            u.z = f2tf32(v.z); u.w = f2tf32(v.w);
            *(uint4*)&Wf[f][kc] = u;
        }
        __syncthreads();

        #pragma unroll
        for (int k8 = 0; k8 < 32; k8 += 8) {
            int col0 = k8 + tig;
            u32 a[2][4], b[4][2];
            #pragma unroll
            for (int mt = 0; mt < 2; mt++) {
                int r0 = warp_m * 32 + mt * 16 + gid;
                a[mt][0] = Xs[r0][col0];
                a[mt][1] = Xs[r0 + 8][col0];
                a[mt][2] = Xs[r0][col0 + 4];
                a[mt][3] = Xs[r0 + 8][col0 + 4];
            }
            #pragma unroll
            for (int nt = 0; nt < 4; nt++) {
                int f0 = warp_n * 32 + nt * 8 + gid;
                b[nt][0] = Wf[f0][col0];
                b[nt][1] = Wf[f0][col0 + 4];
            }
            #pragma unroll
            for (int mt = 0; mt < 2; mt++)
                #pragma unroll
                for (int nt = 0; nt < 4; nt++)
                    mma_tf32(c[mt][nt], a[mt], b[nt]);
        }
        __syncthreads();
    }

    // epilogue: C tile (mt,nt): rows gid / gid+8, cols 2*tig / 2*tig+1
    #pragma unroll
    for (int nt = 0; nt < 4; nt++) {
        int base = fb + warp_n * 32 + nt * 8;   // 8-col block, never straddles regions
        if (base >= Ft) continue;
        int gfc = base + 2 * tig;
        #pragma unroll
        for (int mt = 0; mt < 2; mt++) {
            int r0 = rb + warp_m * 32 + mt * 16 + gid;
            #pragma unroll
            for (int h = 0; h < 2; h++) {
                int row = r0 + h * 8;
                if (row >= n) continue;
                float v0 = c[mt][nt][h * 2 + 0];
                float v1 = c[mt][nt][h * 2 + 1];
                if (base < F0) {
                    v0 += b0 ? b0[gfc] : 0.f;
                    v1 += b0 ? b0[gfc + 1] : 0.f;
                    __half2 p = __floats2half2_rn(v0, v1);
                    *(__half2*)(o0h + (size_t)row * ld0 + gfc) = p;
                } else if (base < F0 + F1) {
                    int lf = gfc - F0;
                    v0 += b1 ? b1[lf] : 0.f;
                    v1 += b1 ? b1[lf + 1] : 0.f;
                    float2 p = make_float2(v0, v1);
                    *(float2*)(o1 + (size_t)row * ld1 + lf) = p;
                } else {
                    int lf = gfc - F0 - F1;
                    v0 += b2 ? b2[lf] : 0.f;
                    v1 += b2 ? b2[lf + 1] : 0.f;
                    float2 p = make_float2(v0, v1);
                    *(float2*)(o2 + (size_t)row * ld2 + lf) = p;
                }
            }
        }
    }
}

// ---------------- conv1 edge term ----------------
__device__ __forceinline__ void term1(
    uint2 u, const float4& xr, const float4& at, float4& acc, float& den)
{
    float2 f0 = __half22float2(*reinterpret_cast<__half2*>(&u.x));
    float2 f1 = __half22float2(*reinterpret_cast<__half2*>(&u.y));
    float m0 = f0.x + xr.x, m1 = f0.y + xr.y, m2 = f1.x + xr.z, m3 = f1.y + xr.w;
    float l = (m0 > 0.f ? m0 : 0.2f * m0) * at.x
            + (m1 > 0.f ? m1 : 0.2f * m1) * at.y
            + (m2 > 0.f ? m2 : 0.2f * m2) * at.z
            + (m3 > 0.f ? m3 : 0.2f * m3) * at.w;
    l += __shfl_xor_sync(0xffffffffu, l, 1);
    l += __shfl_xor_sync(0xffffffffu, l, 2);
    l += __shfl_xor_sync(0xffffffffu, l, 4);
    float a = __expf(l);
    acc.x += a * f0.x; acc.y += a * f0.y; acc.z += a * f1.x; acc.w += a * f1.y;
    den += a;
}

// ---------------- conv1 aggregation: warp per node, 1-deep software pipeline ----------------
__global__ void agg_conv1(int N, const float* __restrict__ att)
{
    int w = (blockIdx.x * blockDim.x + threadIdx.x) >> 5;
    int lane = threadIdx.x & 31;
    if (w >= N) return;
    int beg = g_off[w], end = beg + g_count[w];

    float4 xr = *(const float4*)(g_xr1 + (size_t)w * 128 + lane * 4);
    float4 at = *(const float4*)(att + lane * 4);
    float4 acc = make_float4(0.f, 0.f, 0.f, 0.f);
    float den = 0.f;

    uint2 u_next = make_uint2(0u, 0u);
    if (beg < end) {
        int s0 = g_csr[beg];
        u_next = *(const uint2*)(g_xl1h + (size_t)s0 * 128 + lane * 4);
    }
    {
        uint2 u = *(const uint2*)(g_xl1h + (size_t)w * 128 + lane * 4);
        term1(u, xr, at, acc, den);   // implicit self-loop
    }
    for (int j = beg; j < end; j++) {
        uint2 u = u_next;
        if (j + 1 < end) {
            int sn = g_csr[j + 1];
            u_next = *(const uint2*)(g_xl1h + (size_t)sn * 128 + lane * 4);
        }
        term1(u, xr, at, acc, den);
    }
    float inv = __fdividef(1.f, den + 1e-16f);
    acc.x *= inv; acc.y *= inv; acc.z *= inv; acc.w *= inv;
    *(float4*)(g_agg1 + (size_t)w * 128 + lane * 4) = acc;
}

// ---------------- conv2 aggregation: warp per node, 4 edges per iteration ----------------
__global__ void agg_conv2(int N, const float* __restrict__ att)
{
    int w = (blockIdx.x * blockDim.x + threadIdx.x) >> 5;
    int lane = threadIdx.x & 31;
    if (w >= N) return;
    int beg = g_off[w];
    int T = g_count[w] + 1;
    int grp = lane >> 3, sl = lane & 7;

    float4 xr = *(const float4*)(g_xr2 + (size_t)w * 32 + sl * 4);
    float4 at = *(const float4*)(att + sl * 4);
    float4 acc = make_float4(0.f, 0.f, 0.f, 0.f);
    float den = 0.f;

    for (int t0 = 0; t0 < T; t0 += 4) {
        int t = t0 + grp;
        bool valid = t < T;
        int s = w;
        if (valid && t > 0) s = g_csr[beg + t - 1];
        uint2 u = *(const uint2*)(g_xl2h + (size_t)s * 32 + sl * 4);
        float2 f0 = __half22float2(*reinterpret_cast<__half2*>(&u.x));
        float2 f1 = __half22float2(*reinterpret_cast<__half2*>(&u.y));
        float m0 = f0.x + xr.x, m1 = f0.y + xr.y, m2 = f1.x + xr.z, m3 = f1.y + xr.w;
        float l = (m0 > 0.f ? m0 : 0.2f * m0) * at.x
                + (m1 > 0.f ? m1 : 0.2f * m1) * at.y
                + (m2 > 0.f ? m2 : 0.2f * m2) * at.z
                + (m3 > 0.f ? m3 : 0.2f * m3) * at.w;
        l += __shfl_xor_sync(0xffffffffu, l, 1);
        l += __shfl_xor_sync(0xffffffffu, l, 2);
        l += __shfl_xor_sync(0xffffffffu, l, 4);
        float a = valid ? __expf(l) : 0.f;
        acc.x += a * f0.x; acc.y += a * f0.y; acc.z += a * f1.x; acc.w += a * f1.y;
        den += a;
    }
    #pragma unroll
    for (int o = 8; o <= 16; o <<= 1) {
        acc.x += __shfl_xor_sync(0xffffffffu, acc.x, o);
        acc.y += __shfl_xor_sync(0xffffffffu, acc.y, o);
        acc.z += __shfl_xor_sync(0xffffffffu, acc.z, o);
        acc.w += __shfl_xor_sync(0xffffffffu, acc.w, o);
        den   += __shfl_xor_sync(0xffffffffu, den, o);
    }
    if (lane < 8) {
        float inv = __fdividef(1.f, den + 1e-16f);
        acc.x *= inv; acc.y *= inv; acc.z *= inv; acc.w *= inv;
        *(float4*)(g_agg2 + (size_t)w * 32 + sl * 4) = acc;
    }
}

// ---------------- batch-norm statistics over raw normalized agg (no bias) ----------------
template <int C>
__global__ void bn_stats(const float* __restrict__ h, int n,
                         double* __restrict__ sum, double* __restrict__ sq)
{
    const int Q = C / 4;
    int tid = threadIdx.x;
    float s0 = 0.f, s1 = 0.f, s2v = 0.f, s3 = 0.f;
    float t0 = 0.f, t1 = 0.f, t2 = 0.f, t3 = 0.f;
    size_t total4 = (size_t)n * Q;
    const float4* h4 = (const float4*)h;
    for (size_t j = (size_t)blockIdx.x * blockDim.x + tid; j < total4;
         j += (size_t)gridDim.x * blockDim.x) {
        float4 v = h4[j];
        s0 += v.x; t0 += v.x * v.x;
        s1 += v.y; t1 += v.y * v.y;
        s2v += v.z; t2 += v.z * v.z;
        s3 += v.w; t3 += v.w * v.w;
    }
    __shared__ float red[8][256];
    red[0][tid] = s0; red[1][tid] = s1; red[2][tid] = s2v; red[3][tid] = s3;
    red[4][tid] = t0; red[5][tid] = t1; red[6][tid] = t2; red[7][tid] = t3;
    __syncthreads();
    int q = tid & (Q - 1);
    if (tid < Q) {
        const int G = 256 / Q;
        #pragma unroll
        for (int k = 0; k < 8; k++) {
            float acc = 0.f;
            for (int r = 0; r < G; r++) acc += red[k][q + r * Q];
            if (k < 4) atomicAdd(&sum[q * 4 + k], (double)acc);
            else       atomicAdd(&sq[q * 4 + (k - 4)], (double)acc);
        }
    }
}

// ---------------- BN prep ----------------
__global__ void bn_prep(const double* __restrict__ sum, const double* __restrict__ sq,
                        int n, int C,
                        const float* __restrict__ g, const float* __restrict__ b,
                        float* __restrict__ scale, float* __restrict__ shift)
{
    int c = threadIdx.x;
    if (c >= C) return;
    double mu = sum[c] / n;
    double var = sq[c] / n - mu * mu;
    float istd = rsqrtf((float)var + 1e-5f);
    float sc = istd * g[c];
    scale[c] = sc;
    shift[c] = -(float)mu * sc + b[c];
}

// ---------------- final: BN2 + residual + ELU + [N,32]@[32,2] head ----------------
__global__ void finalize_kernel(const float* __restrict__ linW, const float* __restrict__ linb,
                                float* __restrict__ out, int n)
{
    int gw = (blockIdx.x * blockDim.x + threadIdx.x) >> 5;
    int lane = threadIdx.x & 31;
    if (gw >= n) return;
    float v = g_agg2[(size_t)gw * 32 + lane] * g_scale2[lane] + g_shift2[lane]
            + g_res[(size_t)gw * 32 + lane];
    v = v > 0.f ? v : expm1f(v);
    float o0 = v * linW[lane];
    float o1 = v * linW[32 + lane];
    #pragma unroll
    for (int o = 16; o > 0; o >>= 1) {
        o0 += __shfl_xor_sync(0xffffffffu, o0, o);
        o1 += __shfl_xor_sync(0xffffffffu, o1, o);
    }
    if (lane == 0) {
        out[(size_t)gw * 2] = o0 + linb[0];
        out[(size_t)gw * 2 + 1] = o1 + linb[1];
    }
}

// ---------------- host launcher ----------------
extern "C" void kernel_launch(void* const* d_in, const int* in_sizes, int n_in,
                              void* d_out, int out_size)
{
    const float* x      = (const float*)d_in[0];
    const int*   ei     = (const int*)d_in[1];
    const float* Wl1    = (const float*)d_in[2];
    const float* bl1    = (const float*)d_in[3];
    const float* Wr1    = (const float*)d_in[4];
    const float* br1    = (const float*)d_in[5];
    const float* att1   = (const float*)d_in[6];
    const float* Wl2    = (const float*)d_in[8];
    const float* bl2    = (const float*)d_in[9];
    const float* Wr2    = (const float*)d_in[10];
    const float* br2    = (const float*)d_in[11];
    const float* att2   = (const float*)d_in[12];
    const float* bn1_g  = (const float*)d_in[14];
    const float* bn1_b  = (const float*)d_in[15];
    const float* bn2_g  = (const float*)d_in[16];
    const float* bn2_b  = (const float*)d_in[17];
    const float* skipW  = (const float*)d_in[18];
    const float* linW   = (const float*)d_in[19];
    const float* linb   = (const float*)d_in[20];
    float* out = (float*)d_out;
    // bias1/bias2 (d_in[7], d_in[13]) fold out of BN exactly (mean shift)

    const int N = in_sizes[0] / 128;
    const int E = in_sizes[1] / 2;

    void* p;
    cudaGetSymbolAddress(&p, g_count); cudaMemsetAsync(p, 0, (size_t)N * sizeof(int));
    cudaGetSymbolAddress(&p, g_total); cudaMemsetAsync(p, 0, sizeof(int));
    cudaGetSymbolAddress(&p, g_sum1);  cudaMemsetAsync(p, 0, 128 * sizeof(double));
    cudaGetSymbolAddress(&p, g_sq1);   cudaMemsetAsync(p, 0, 128 * sizeof(double));
    cudaGetSymbolAddress(&p, g_sum2);  cudaMemsetAsync(p, 0, 32 * sizeof(double));
    cudaGetSymbolAddress(&p, g_sq2);   cudaMemsetAsync(p, 0, 32 * sizeof(double));

    __half *d_xl1h, *d_xl2h;
    float *d_xr1, *d_res, *d_xr2, *d_agg1, *d_agg2;
    float *d_scale1, *d_shift1, *d_scale2, *d_shift2;
    double *d_sum1, *d_sq1, *d_sum2, *d_sq2;
    cudaGetSymbolAddress((void**)&d_xl1h, g_xl1h);
    cudaGetSymbolAddress((void**)&d_xr1, g_xr1);
    cudaGetSymbolAddress((void**)&d_res, g_res);
    cudaGetSymbolAddress((void**)&d_xl2h, g_xl2h);
    cudaGetSymbolAddress((void**)&d_xr2, g_xr2);
    cudaGetSymbolAddress((void**)&d_agg1, g_agg1);
    cudaGetSymbolAddress((void**)&d_agg2, g_agg2);
    cudaGetSymbolAddress((void**)&d_scale1, g_scale1);
    cudaGetSymbolAddress((void**)&d_shift1, g_shift1);
    cudaGetSymbolAddress((void**)&d_scale2, g_scale2);
    cudaGetSymbolAddress((void**)&d_shift2, g_shift2);
    cudaGetSymbolAddress((void**)&d_sum1, g_sum1);
    cudaGetSymbolAddress((void**)&d_sq1, g_sq1);
    cudaGetSymbolAddress((void**)&d_sum2, g_sum2);
    cudaGetSymbolAddress((void**)&d_sq2, g_sq2);

    const int rowBlocks = (N + 127) / 128;
    const int nodeWarpBlocks = (N * 32 + 255) / 256;

    // ---- fork a side stream for the CSR build (independent of transform1) ----
    cudaStream_t s2;
    cudaEvent_t eFork, eJoin;
    bool forked = (cudaStreamCreateWithFlags(&s2, cudaStreamNonBlocking) == cudaSuccess)
               && (cudaEventCreateWithFlags(&eFork, cudaEventDisableTiming) == cudaSuccess)
               && (cudaEventCreateWithFlags(&eJoin, cudaEventDisableTiming) == cudaSuccess);

    if (forked) {
        cudaEventRecord(eFork, 0);          // after memsets on the origin stream
        cudaStreamWaitEvent(s2, eFork, 0);
        csr_hist<<<(E + 255) / 256, 256, 0, s2>>>(ei, E);
        csr_alloc<<<(N + 255) / 256, 256, 0, s2>>>(N);
        csr_scatter<<<(E + 255) / 256, 256, 0, s2>>>(ei, E);
        cudaEventRecord(eJoin, s2);
    } else {
        csr_hist<<<(E + 255) / 256, 256>>>(ei, E);
        csr_alloc<<<(N + 255) / 256, 256>>>(N);
        csr_scatter<<<(E + 255) / 256, 256>>>(ei, E);
    }

    // conv1 transforms + residual: overlaps with the CSR build
    transform_kernel<<<dim3(rowBlocks, 5), 256>>>(
        x, N, Wl1, Wr1, skipW, 128, 128, 32,
        bl1, br1, nullptr,
        d_xl1h, d_xr1, d_res, 128, 128, 32,
        nullptr, nullptr);

    if (forked) cudaStreamWaitEvent(0, eJoin, 0);   // join before agg (needs CSR + xl1h)

    agg_conv1<<<nodeWarpBlocks, 256>>>(N, att1);

    bn_stats<128><<<256, 256>>>(d_agg1, N, d_sum1, d_sq1);
    bn_prep<<<1, 128>>>(d_sum1, d_sq1, N, 128, bn1_g, bn1_b, d_scale1, d_shift1);

    // conv2 transforms reading agg1 with on-the-fly BN + ELU
    transform_kernel<<<dim3(rowBlocks, 1), 256>>>(
        d_agg1, N, Wl2, Wr2, nullptr, 32, 32, 0,
        bl2, br2, nullptr,
        d_xl2h, d_xr2, nullptr, 32, 32, 0,
        d_scale1, d_shift1);

    agg_conv2<<<nodeWarpBlocks, 256>>>(N, att2);

    bn_stats<32><<<256, 256>>>(d_agg2, N, d_sum2, d_sq2);
    bn_prep<<<1, 32>>>(d_sum2, d_sq2, N, 32, bn2_g, bn2_b, d_scale2, d_shift2);

    finalize_kernel<<<nodeWarpBlocks, 256>>>(linW, linb, out, N);
    // NOTE: s2/eFork/eJoin intentionally not destroyed — destroying a stream
    // participating in capture invalidates the graph; leak bounded by ~3 host calls.
}